// round 3
// baseline (speedup 1.0000x reference)
#include <cuda_runtime.h>
#include <cuda_bf16.h>
#include <stdint.h>

#define NB 2048      // anchors
#define NP 4         // positives per anchor
#define ND 256       // dim
#define NN 32768     // negatives
#define BM 128       // CTA tile M
#define BN 256       // CTA tile N
#define KCB 64       // K chunk bytes (s8) per stage
#define NCH (ND / KCB)   // 4 chunks
#define NST 3            // pipeline stages
#define NYT (NN / BN)    // 128 col-tiles
#define INV_T 20.0f
#define SHIFT_C 28.853900817779268f  // 20 * log2(e)

// smem layout (bytes)
#define SROW_OFF 0            // 128 floats
#define SSN_OFF  512          // 256 floats (col scales * SHIFT_C)
#define SSA_OFF  1536         // 128 floats (row scales)
#define SA_OFF   2048
#define SA_STG   (128 * 80)   // 10240 (80B padded rows, conflict-free ldmatrix)
#define SB_OFF   (SA_OFF + NST * SA_STG)        // 32768
#define SB_STG   (256 * 80)   // 20480
#define SMEM_TOTAL (SB_OFF + NST * SB_STG)      // 94208

// ---------------- scratch ----------------
__device__ int8_t g_qa[NB * ND];
__device__ int8_t g_qn[NN * ND];
__device__ float g_sa[NB];
__device__ float g_sn[NN];
__device__ float g_pos[NB * NP];
__device__ float g_part[NB * NYT];
__device__ float g_lse[NB];

// ---------------- helpers ----------------
__device__ __forceinline__ float wredsum(float v) {
#pragma unroll
    for (int o = 16; o; o >>= 1) v += __shfl_xor_sync(0xffffffffu, v, o);
    return v;
}
__device__ __forceinline__ float wredmax(float v) {
#pragma unroll
    for (int o = 16; o; o >>= 1) v = fmaxf(v, __shfl_xor_sync(0xffffffffu, v, o));
    return v;
}
__device__ __forceinline__ float ex2(float x) {
    float y;
    asm("ex2.approx.f32 %0, %1;" : "=f"(y) : "f"(x));
    return y;
}
__device__ __forceinline__ float logaddexp_(float x, float y) {
    float m = fmaxf(x, y);
    float d = fminf(x, y) - m;
    return m + log1pf(__expf(d));
}
__device__ __forceinline__ void cpa16(uint32_t sdst, const void* gsrc) {
    asm volatile("cp.async.cg.shared.global [%0], [%1], 16;\n" :: "r"(sdst), "l"(gsrc));
}
__device__ __forceinline__ int pack4(float x0, float x1, float x2, float x3, float qs) {
    int q0 = __float2int_rn(x0 * qs), q1 = __float2int_rn(x1 * qs);
    int q2 = __float2int_rn(x2 * qs), q3 = __float2int_rn(x3 * qs);
    return (q0 & 255) | ((q1 & 255) << 8) | ((q2 & 255) << 16) | ((q3 & 255) << 24);
}

// ---------------- kernel 1: normalize + quantize (anchors & negatives) + pos_sim ----------------
// one warp per row; rows [0,NB) = anchors, [NB, NB+NN) = negatives
__global__ void k_prep(const float* __restrict__ a, const float* __restrict__ p,
                       const float* __restrict__ n) {
    int w = (blockIdx.x * blockDim.x + threadIdx.x) >> 5;
    int lane = threadIdx.x & 31;
    if (w >= NB + NN) return;

    bool is_anchor = (w < NB);
    const float* src = is_anchor ? (a + (size_t)w * ND)
                                 : (n + (size_t)(w - NB) * ND);
    const float4* sr = (const float4*)src;
    float4 v0 = sr[lane], v1 = sr[lane + 32];
    float ss = v0.x*v0.x + v0.y*v0.y + v0.z*v0.z + v0.w*v0.w
             + v1.x*v1.x + v1.y*v1.y + v1.z*v1.z + v1.w*v1.w;
    ss = wredsum(ss);
    float inv = 1.0f / fmaxf(sqrtf(ss), 1e-12f);
    v0.x *= inv; v0.y *= inv; v0.z *= inv; v0.w *= inv;
    v1.x *= inv; v1.y *= inv; v1.z *= inv; v1.w *= inv;

    // per-row absmax -> symmetric int8 quant
    float mx = fmaxf(fmaxf(fmaxf(fabsf(v0.x), fabsf(v0.y)), fmaxf(fabsf(v0.z), fabsf(v0.w))),
                     fmaxf(fmaxf(fabsf(v1.x), fabsf(v1.y)), fmaxf(fabsf(v1.z), fabsf(v1.w))));
    mx = fmaxf(wredmax(mx), 1e-20f);
    float qs = 127.0f / mx;

    int* qdst = is_anchor ? (int*)(g_qa + (size_t)w * ND)
                          : (int*)(g_qn + (size_t)(w - NB) * ND);
    qdst[lane]      = pack4(v0.x, v0.y, v0.z, v0.w, qs);
    qdst[32 + lane] = pack4(v1.x, v1.y, v1.z, v1.w, qs);
    if (lane == 0) {
        if (is_anchor) g_sa[w] = mx * (1.0f / 127.0f);
        else           g_sn[w - NB] = mx * (1.0f / 127.0f);
    }

    if (is_anchor) {
#pragma unroll
        for (int j = 0; j < NP; j++) {
            const float4* pr = (const float4*)(p + (size_t)(w * NP + j) * ND);
            float4 p0 = pr[lane], p1 = pr[lane + 32];
            float ssp = p0.x*p0.x + p0.y*p0.y + p0.z*p0.z + p0.w*p0.w
                      + p1.x*p1.x + p1.y*p1.y + p1.z*p1.z + p1.w*p1.w;
            float dp  = v0.x*p0.x + v0.y*p0.y + v0.z*p0.z + v0.w*p0.w
                      + v1.x*p1.x + v1.y*p1.y + v1.z*p1.z + v1.w*p1.w;
            ssp = wredsum(ssp);
            dp  = wredsum(dp);
            if (lane == 0)
                g_pos[w * NP + j] = dp / fmaxf(sqrtf(ssp), 1e-12f) * INV_T;
        }
    }
}

// ---------------- kernel 2: int8 IMMA GEMM + fused exp-sum epilogue ----------------
// grid (16, 128), 512 threads, warps 2(M)x8(N), warp tile 64x32, 3-stage cp.async.
__device__ __forceinline__ void load_chunk(uint32_t sb, int rowBase, int colBase,
                                           int kc, int buf, int tid) {
    const int k0 = kc * KCB;
    {   // A: 128 rows x 4 x 16B = 512 chunks (one per thread)
        int r = tid >> 2, c = tid & 3;
        cpa16(sb + SA_OFF + buf * SA_STG + r * 80 + c * 16,
              g_qa + (size_t)(rowBase + r) * ND + k0 + c * 16);
    }
#pragma unroll
    for (int it = 0; it < 2; it++) {  // B: 256 rows x 4 = 1024 chunks
        int idx = tid + it * 512;
        int r = idx >> 2, c = idx & 3;
        cpa16(sb + SB_OFF + buf * SB_STG + r * 80 + c * 16,
              g_qn + (size_t)(colBase + r) * ND + k0 + c * 16);
    }
    asm volatile("cp.async.commit_group;\n" ::: "memory");
}

__global__ void __launch_bounds__(512, 1) k_gemm() {
    extern __shared__ __align__(1024) char smem[];
    const uint32_t sb = (uint32_t)__cvta_generic_to_shared(smem);
    float* s_row = (float*)(smem + SROW_OFF);
    float* s_sn  = (float*)(smem + SSN_OFF);
    float* s_sa  = (float*)(smem + SSA_OFF);

    const int tid = threadIdx.x, lane = tid & 31, warp = tid >> 5;
    const int wm = warp >> 3, wn = warp & 7;
    const int rowBase = blockIdx.x * BM, colBase = blockIdx.y * BN;

    // prologue loads + scales
    load_chunk(sb, rowBase, colBase, 0, 0, tid);
    load_chunk(sb, rowBase, colBase, 1, 1, tid);
    if (tid < 256) s_sn[tid] = g_sn[colBase + tid] * SHIFT_C;
    if (tid < 128) { s_sa[tid] = g_sa[rowBase + tid]; s_row[tid] = 0.0f; }

    int acc[4][4][4];
#pragma unroll
    for (int mi = 0; mi < 4; mi++)
#pragma unroll
        for (int ni = 0; ni < 4; ni++)
#pragma unroll
            for (int r = 0; r < 4; r++) acc[mi][ni][r] = 0;

#pragma unroll
    for (int kc = 0; kc < NCH; kc++) {
        asm volatile("cp.async.wait_group %0;\n" :: "n"(NST - 2) : "memory");
        __syncthreads();
        if (kc + 2 < NCH)
            load_chunk(sb, rowBase, colBase, kc + 2, (kc + 2) % NST, tid);

        const uint32_t aBase = sb + SA_OFF + (kc % NST) * SA_STG;
        const uint32_t bBase = sb + SB_OFF + (kc % NST) * SB_STG;
#pragma unroll
        for (int s = 0; s < 2; s++) {  // two k32 steps per 64B chunk
            const int kb = s * 32;
            uint32_t af[4][4], bf[2][4];
#pragma unroll
            for (int mi = 0; mi < 4; mi++) {
                uint32_t ad = aBase + (uint32_t)(wm * 64 + mi * 16 + (lane & 15)) * 80
                            + kb + ((lane >> 4) << 4);
                asm volatile("ldmatrix.sync.aligned.m8n8.x4.shared.b16 {%0,%1,%2,%3}, [%4];\n"
                             : "=r"(af[mi][0]), "=r"(af[mi][1]), "=r"(af[mi][2]), "=r"(af[mi][3])
                             : "r"(ad));
            }
#pragma unroll
            for (int bp = 0; bp < 2; bp++) {
                int nrow = wn * 32 + bp * 16 + (lane & 7) + ((lane >> 4) << 3);
                uint32_t bd = bBase + (uint32_t)nrow * 80 + kb + (((lane >> 3) & 1) << 4);
                asm volatile("ldmatrix.sync.aligned.m8n8.x4.shared.b16 {%0,%1,%2,%3}, [%4];\n"
                             : "=r"(bf[bp][0]), "=r"(bf[bp][1]), "=r"(bf[bp][2]), "=r"(bf[bp][3])
                             : "r"(bd));
            }
#pragma unroll
            for (int mi = 0; mi < 4; mi++)
#pragma unroll
                for (int ni = 0; ni < 4; ni++) {
                    const uint32_t b0 = bf[ni >> 1][(ni & 1) * 2];
                    const uint32_t b1 = bf[ni >> 1][(ni & 1) * 2 + 1];
                    asm volatile(
                        "mma.sync.aligned.m16n8k32.row.col.s32.s8.s8.s32 "
                        "{%0,%1,%2,%3},{%4,%5,%6,%7},{%8,%9},{%0,%1,%2,%3};\n"
                        : "+r"(acc[mi][ni][0]), "+r"(acc[mi][ni][1]),
                          "+r"(acc[mi][ni][2]), "+r"(acc[mi][ni][3])
                        : "r"(af[mi][0]), "r"(af[mi][1]), "r"(af[mi][2]), "r"(af[mi][3]),
                          "r"(b0), "r"(b1));
                }
        }
    }

    // epilogue: exp2(i2f(acc)*sa*(sn*C) - C), per-row sums (deterministic partials)
#pragma unroll
    for (int mi = 0; mi < 4; mi++) {
#pragma unroll
        for (int h = 0; h < 2; h++) {
            int row_local = wm * 64 + mi * 16 + h * 8 + (lane >> 2);
            float sa = s_sa[row_local];
            float ssum = 0.0f;
#pragma unroll
            for (int ni = 0; ni < 4; ni++) {
                int n0 = wn * 32 + ni * 8 + (lane & 3) * 2;
                float f0 = __int2float_rn(acc[mi][ni][2 * h])     * sa;
                float f1 = __int2float_rn(acc[mi][ni][2 * h + 1]) * sa;
                ssum += ex2(fmaf(f0, s_sn[n0],     -SHIFT_C));
                ssum += ex2(fmaf(f1, s_sn[n0 + 1], -SHIFT_C));
            }
            ssum += __shfl_xor_sync(0xffffffffu, ssum, 1);
            ssum += __shfl_xor_sync(0xffffffffu, ssum, 2);
            if ((lane & 3) == 0) atomicAdd(&s_row[row_local], ssum);
        }
    }
    __syncthreads();
    if (tid < 128)
        g_part[(size_t)(rowBase + tid) * NYT + blockIdx.y] = s_row[tid];
}

// ---------------- kernel 3: reduce partials -> lse ----------------
__global__ void k_reduce() {
    int w = (blockIdx.x * blockDim.x + threadIdx.x) >> 5;
    int lane = threadIdx.x & 31;
    if (w >= NB) return;
    const float* sp = g_part + (size_t)w * NYT;
    float s = 0.0f;
#pragma unroll
    for (int j = 0; j < NYT / 32; j++) s += sp[lane + 32 * j];
    s = wredsum(s);
    if (lane == 0) g_lse[w] = logf(s) + 20.0f;
}

// ---------------- kernel 4: finalize ----------------
__global__ void k_final(const int* __restrict__ cnt, float* __restrict__ out) {
    float local = 0.0f;
    for (int b = threadIdx.x; b < NB; b += 256) {
        float lse = g_lse[b];
        int c = cnt[b];
        float ps[NP];
#pragma unroll
        for (int j = 0; j < NP; j++) ps[j] = g_pos[b * NP + j];

        float m = ps[0];
#pragma unroll
        for (int j = 1; j < NP; j++) m = fmaxf(m, ps[j]);
        float Z = 0.0f, W = 0.0f;
#pragma unroll
        for (int j = 0; j < NP; j++) {
            float w = __expf(ps[j] - m);
            Z += w;
            W += w * ps[j];
        }
        float wps = W / Z;

#pragma unroll
        for (int j = 0; j < NP; j++)
            if (j < c) local += logaddexp_(ps[j], lse) - ps[j];
        if (c > 1) local += 0.1f * (logaddexp_(wps, lse) - wps);
    }

    __shared__ float red[256];
    red[threadIdx.x] = local;
    __syncthreads();
#pragma unroll
    for (int o = 128; o; o >>= 1) {
        if (threadIdx.x < o) red[threadIdx.x] += red[threadIdx.x + o];
        __syncthreads();
    }
    if (threadIdx.x == 0) out[0] = red[0] / (float)NB;
}

// ---------------- launch ----------------
extern "C" void kernel_launch(void* const* d_in, const int* in_sizes, int n_in,
                              void* d_out, int out_size) {
    const float* a = (const float*)d_in[0];
    const float* p = (const float*)d_in[1];
    const float* n = (const float*)d_in[2];
    const int* cnt = (const int*)d_in[3];

    cudaFuncSetAttribute(k_gemm, cudaFuncAttributeMaxDynamicSharedMemorySize, SMEM_TOTAL);

    k_prep<<<(NB + NN) / 8, 256>>>(a, p, n);
    k_gemm<<<dim3(NB / BM, NYT), 512, SMEM_TOTAL>>>();
    k_reduce<<<NB / 8, 256>>>();
    k_final<<<1, 256>>>(cnt, (float*)d_out);
}

// round 4
// speedup vs baseline: 3.1974x; 3.1974x over previous
#include <cuda_runtime.h>
#include <cuda_bf16.h>
#include <stdint.h>

#define NB 2048      // anchors
#define NP 4         // positives per anchor
#define ND 256       // dim
#define NN 32768     // negatives
#define BM 128       // CTA tile M
#define BN 128       // CTA tile N
#define KC 64        // K chunk (bf16) -> 128B rows
#define NCH (ND / KC)    // 4 chunks
#define NST 3            // pipeline stages
#define NYT (NN / BN)    // 256 col-tiles
#define INV_T 20.0f
#define SHIFT_C 28.853900817779268f  // 20 * log2(e)

// smem layout (bytes)
#define SROW_OFF 0                        // 128 floats
#define SA_OFF   1024
#define SA_STG   (BM * 128)               // 16384
#define SB_OFF   (SA_OFF + NST * SA_STG)  // 50176
#define SB_STG   (BN * 128)               // 16384
#define SMEM_TOTAL (SB_OFF + NST * SB_STG)  // 99328 -> 2 CTAs/SM

// ---------------- scratch ----------------
__device__ __nv_bfloat16 g_a[NB * ND];
__device__ __nv_bfloat16 g_n[NN * ND];
__device__ float g_pos[NB * NP];
__device__ float g_part[NB * NYT];
__device__ float g_loss[NB];

// ---------------- helpers ----------------
__device__ __forceinline__ float wredsum(float v) {
#pragma unroll
    for (int o = 16; o; o >>= 1) v += __shfl_xor_sync(0xffffffffu, v, o);
    return v;
}
__device__ __forceinline__ float ex2(float x) {
    float y;
    asm("ex2.approx.f32 %0, %1;" : "=f"(y) : "f"(x));
    return y;
}
__device__ __forceinline__ float logaddexp_(float x, float y) {
    float m = fmaxf(x, y);
    float d = fminf(x, y) - m;
    return m + log1pf(__expf(d));
}
__device__ __forceinline__ void cpa16(uint32_t sdst, const void* gsrc) {
    asm volatile("cp.async.cg.shared.global [%0], [%1], 16;\n" :: "r"(sdst), "l"(gsrc));
}

// ---------------- kernel 1: normalize -> bf16 (anchors & negatives) + fp32 pos_sim ----------------
__global__ void k_prep(const float* __restrict__ a, const float* __restrict__ p,
                       const float* __restrict__ n) {
    int w = (blockIdx.x * blockDim.x + threadIdx.x) >> 5;
    int lane = threadIdx.x & 31;
    if (w >= NB + NN) return;

    bool is_anchor = (w < NB);
    const float4* sr = is_anchor ? (const float4*)(a + (size_t)w * ND)
                                 : (const float4*)(n + (size_t)(w - NB) * ND);
    float4 v0 = sr[lane], v1 = sr[lane + 32];
    float ss = v0.x*v0.x + v0.y*v0.y + v0.z*v0.z + v0.w*v0.w
             + v1.x*v1.x + v1.y*v1.y + v1.z*v1.z + v1.w*v1.w;
    ss = wredsum(ss);
    float inv = 1.0f / fmaxf(sqrtf(ss), 1e-12f);
    v0.x *= inv; v0.y *= inv; v0.z *= inv; v0.w *= inv;
    v1.x *= inv; v1.y *= inv; v1.z *= inv; v1.w *= inv;

    __nv_bfloat162* gr = is_anchor ? (__nv_bfloat162*)(g_a + (size_t)w * ND)
                                   : (__nv_bfloat162*)(g_n + (size_t)(w - NB) * ND);
    gr[2*lane]        = __floats2bfloat162_rn(v0.x, v0.y);
    gr[2*lane + 1]    = __floats2bfloat162_rn(v0.z, v0.w);
    gr[64 + 2*lane]   = __floats2bfloat162_rn(v1.x, v1.y);
    gr[64 + 2*lane+1] = __floats2bfloat162_rn(v1.z, v1.w);

    if (is_anchor) {
#pragma unroll
        for (int j = 0; j < NP; j++) {
            const float4* pr = (const float4*)(p + (size_t)(w * NP + j) * ND);
            float4 p0 = pr[lane], p1 = pr[lane + 32];
            float ssp = p0.x*p0.x + p0.y*p0.y + p0.z*p0.z + p0.w*p0.w
                      + p1.x*p1.x + p1.y*p1.y + p1.z*p1.z + p1.w*p1.w;
            float dp  = v0.x*p0.x + v0.y*p0.y + v0.z*p0.z + v0.w*p0.w
                      + v1.x*p1.x + v1.y*p1.y + v1.z*p1.z + v1.w*p1.w;
            ssp = wredsum(ssp);
            dp  = wredsum(dp);
            if (lane == 0)
                g_pos[w * NP + j] = dp / fmaxf(sqrtf(ssp), 1e-12f) * INV_T;
        }
    }
}

// ---------------- kernel 2: bf16 HMMA GEMM + fused exp-sum epilogue ----------------
// grid (16, 256), 256 threads, 2 CTAs/SM. warps 2(M)x4(N), warp tile 64x32.
// smem: XOR-swizzled 128B rows: off = r*128 + ((c ^ (r&7))<<4), c = 16B-slice idx.
__device__ __forceinline__ void load_chunk(uint32_t sb, int rowBase, int colBase,
                                           int kc, int stage, int tid) {
    const int k0 = kc * KC;
    const uint32_t aBase = sb + SA_OFF + stage * SA_STG;
    const uint32_t bBase = sb + SB_OFF + stage * SB_STG;
#pragma unroll
    for (int it = 0; it < 4; it++) {
        int idx = tid + it * 256;
        int r = idx >> 3, c = idx & 7;
        uint32_t off = (uint32_t)(r * 128) + (uint32_t)((c ^ (r & 7)) << 4);
        cpa16(aBase + off, g_a + (size_t)(rowBase + r) * ND + k0 + c * 8);
    }
#pragma unroll
    for (int it = 0; it < 4; it++) {
        int idx = tid + it * 256;
        int r = idx >> 3, c = idx & 7;
        uint32_t off = (uint32_t)(r * 128) + (uint32_t)((c ^ (r & 7)) << 4);
        cpa16(bBase + off, g_n + (size_t)(colBase + r) * ND + k0 + c * 8);
    }
    asm volatile("cp.async.commit_group;\n" ::: "memory");
}

__global__ void __launch_bounds__(256, 2) k_gemm() {
    extern __shared__ __align__(1024) char smem[];
    const uint32_t sb = (uint32_t)__cvta_generic_to_shared(smem);
    float* s_row = (float*)(smem + SROW_OFF);

    const int tid = threadIdx.x, lane = tid & 31, warp = tid >> 5;
    const int wm = warp >> 2, wn = warp & 3;
    const int rowBase = blockIdx.x * BM, colBase = blockIdx.y * BN;
    const int x7 = lane & 7;

    if (tid < BM) s_row[tid] = 0.0f;

    // precomputed swizzle bases (kstep term added per-ks: ko = ((2ks ^ (x7&6))<<4))
    uint32_t baseA[4], baseB[2];
    {
        int hi = (lane >> 4) & 1;                    // A: 16B half within k16
        int arow = wm * 64 + (lane & 15);
#pragma unroll
        for (int mi = 0; mi < 4; mi++)
            baseA[mi] = sb + SA_OFF + (uint32_t)((arow + mi * 16) * 128)
                      + (uint32_t)((hi ^ (x7 & 1)) << 4);
        int m = lane >> 3;                            // B trans: matrix idx
        int nb = m >> 1, kh = m & 1;
        int brow0 = wn * 32 + nb * 8 + x7;
#pragma unroll
        for (int ni2 = 0; ni2 < 2; ni2++)
            baseB[ni2] = sb + SB_OFF + (uint32_t)((brow0 + ni2 * 16) * 128)
                       + (uint32_t)((kh ^ (x7 & 1)) << 4);
    }

    float acc[4][4][4];
#pragma unroll
    for (int mi = 0; mi < 4; mi++)
#pragma unroll
        for (int ni = 0; ni < 4; ni++)
#pragma unroll
            for (int r = 0; r < 4; r++) acc[mi][ni][r] = 0.0f;

    load_chunk(sb, rowBase, colBase, 0, 0, tid);
    load_chunk(sb, rowBase, colBase, 1, 1, tid);

#pragma unroll
    for (int kc = 0; kc < NCH; kc++) {
        if (kc < NCH - 1)
            asm volatile("cp.async.wait_group 1;\n" ::: "memory");
        else
            asm volatile("cp.async.wait_group 0;\n" ::: "memory");
        __syncthreads();
        if (kc + 2 < NCH)
            load_chunk(sb, rowBase, colBase, kc + 2, (kc + 2) % NST, tid);

        const uint32_t stgOff = (uint32_t)((kc % NST) * SA_STG);  // same stride A/B
#pragma unroll
        for (int ks = 0; ks < 4; ks++) {
            const uint32_t ko = (uint32_t)((((2 * ks) ^ (x7 & 6))) << 4);
            uint32_t af[4][4], bf[2][4];
#pragma unroll
            for (int mi = 0; mi < 4; mi++)
                asm volatile("ldmatrix.sync.aligned.m8n8.x4.shared.b16 {%0,%1,%2,%3}, [%4];\n"
                             : "=r"(af[mi][0]), "=r"(af[mi][1]), "=r"(af[mi][2]), "=r"(af[mi][3])
                             : "r"(baseA[mi] + stgOff + ko));
#pragma unroll
            for (int ni2 = 0; ni2 < 2; ni2++)
                asm volatile("ldmatrix.sync.aligned.m8n8.x4.trans.shared.b16 {%0,%1,%2,%3}, [%4];\n"
                             : "=r"(bf[ni2][0]), "=r"(bf[ni2][1]), "=r"(bf[ni2][2]), "=r"(bf[ni2][3])
                             : "r"(baseB[ni2] + stgOff + ko));
#pragma unroll
            for (int mi = 0; mi < 4; mi++)
#pragma unroll
                for (int ni = 0; ni < 4; ni++)
                    asm volatile("mma.sync.aligned.m16n8k16.row.col.f32.bf16.bf16.f32 "
                                 "{%0,%1,%2,%3},{%4,%5,%6,%7},{%8,%9},{%0,%1,%2,%3};\n"
                                 : "+f"(acc[mi][ni][0]), "+f"(acc[mi][ni][1]),
                                   "+f"(acc[mi][ni][2]), "+f"(acc[mi][ni][3])
                                 : "r"(af[mi][0]), "r"(af[mi][1]), "r"(af[mi][2]), "r"(af[mi][3]),
                                   "r"(bf[ni >> 1][(ni & 1) * 2]), "r"(bf[ni >> 1][(ni & 1) * 2 + 1]));
        }
    }

    // epilogue: exp2(acc*C - C), per-row sums, deterministic per-(row, coltile) partials
#pragma unroll
    for (int mi = 0; mi < 4; mi++) {
#pragma unroll
        for (int h = 0; h < 2; h++) {
            float ssum = 0.0f;
#pragma unroll
            for (int ni = 0; ni < 4; ni++) {
                ssum += ex2(fmaf(acc[mi][ni][2 * h],     SHIFT_C, -SHIFT_C));
                ssum += ex2(fmaf(acc[mi][ni][2 * h + 1], SHIFT_C, -SHIFT_C));
            }
            ssum += __shfl_xor_sync(0xffffffffu, ssum, 1);
            ssum += __shfl_xor_sync(0xffffffffu, ssum, 2);
            if ((lane & 3) == 0)
                atomicAdd(&s_row[wm * 64 + mi * 16 + h * 8 + (lane >> 2)], ssum);
        }
    }
    __syncthreads();
    if (tid < BM)
        g_part[(size_t)(rowBase + tid) * NYT + blockIdx.y] = s_row[tid];
}

// ---------------- kernel 3: reduce partials -> per-anchor loss (fused) ----------------
__global__ void k_reduce(const int* __restrict__ cnt) {
    int w = (blockIdx.x * blockDim.x + threadIdx.x) >> 5;
    int lane = threadIdx.x & 31;
    if (w >= NB) return;
    const float* sp = g_part + (size_t)w * NYT;
    float s = 0.0f;
#pragma unroll
    for (int j = 0; j < NYT / 32; j++) s += sp[lane + 32 * j];
    s = wredsum(s);
    if (lane == 0) {
        float lse = logf(s) + 20.0f;
        int c = cnt[w];
        float ps[NP];
#pragma unroll
        for (int j = 0; j < NP; j++) ps[j] = g_pos[w * NP + j];

        float m = ps[0];
#pragma unroll
        for (int j = 1; j < NP; j++) m = fmaxf(m, ps[j]);
        float Z = 0.0f, W = 0.0f;
#pragma unroll
        for (int j = 0; j < NP; j++) {
            float e = __expf(ps[j] - m);
            Z += e;
            W += e * ps[j];
        }
        float wps = W / Z;

        float local = 0.0f;
#pragma unroll
        for (int j = 0; j < NP; j++)
            if (j < c) local += logaddexp_(ps[j], lse) - ps[j];
        if (c > 1) local += 0.1f * (logaddexp_(wps, lse) - wps);
        g_loss[w] = local;
    }
}

// ---------------- kernel 4: final sum ----------------
__global__ void k_final(float* __restrict__ out) {
    float local = 0.0f;
#pragma unroll
    for (int j = 0; j < NB / 256; j++) local += g_loss[threadIdx.x + 256 * j];

    __shared__ float red[256];
    red[threadIdx.x] = local;
    __syncthreads();
#pragma unroll
    for (int o = 128; o; o >>= 1) {
        if (threadIdx.x < o) red[threadIdx.x] += red[threadIdx.x + o];
        __syncthreads();
    }
    if (threadIdx.x == 0) out[0] = red[0] / (float)NB;
}

// ---------------- launch ----------------
extern "C" void kernel_launch(void* const* d_in, const int* in_sizes, int n_in,
                              void* d_out, int out_size) {
    const float* a = (const float*)d_in[0];
    const float* p = (const float*)d_in[1];
    const float* n = (const float*)d_in[2];
    const int* cnt = (const int*)d_in[3];

    cudaFuncSetAttribute(k_gemm, cudaFuncAttributeMaxDynamicSharedMemorySize, SMEM_TOTAL);

    k_prep<<<(NB + NN) / 8, 256>>>(a, p, n);
    k_gemm<<<dim3(NB / BM, NYT), 256, SMEM_TOTAL>>>();
    k_reduce<<<NB / 8, 256>>>(cnt);
    k_final<<<1, 256>>>((float*)d_out);
}